// round 2
// baseline (speedup 1.0000x reference)
#include <cuda_runtime.h>
#include <math.h>

#define NP    8192
#define INC   256
#define SCC   64
#define OUTC  256
#define KPN   15
#define KNN_TPB 64
#define BUFCAP 160

// ---------------- scratch (__device__ globals, no allocations) ----------------
__device__ __align__(256) float g_h   [2 * NP * SCC];               // 4 MB
__device__ __align__(256) int   g_idx [2 * NP * 32];                // 2 MB
__device__ __align__(256) int   g_cnt [2 * NP];
__device__ __align__(256) float g_agg [(size_t)2 * NP * KPN * SCC]; // 60 MB
__device__ __align__(256) float g_h2  [2 * NP * SCC];               // 4 MB
__device__ __align__(256) float g_part[2 * 2 * 32 * OUTC];
__device__ __align__(256) float g_mu  [2 * OUTC];
__device__ __align__(256) float g_rstd[2 * OUTC];

// ---------------- generic 64xN tiled fp32 GEMM: C = A @ B (+bias) ----------------
// blockDim 256, tile 64x64, BK=32. grid.z selects A0/A1 (two clouds), C strided.
__global__ __launch_bounds__(256) void gemm_k(
    const float* __restrict__ A0, const float* __restrict__ A1,
    const float* __restrict__ B,  const float* __restrict__ bias,
    float* __restrict__ C, int M, int N, int K, size_t strideC)
{
    __shared__ __align__(16) float As[32][65];   // As[k][m], pad avoids conflicts
    __shared__ __align__(16) float Bs[32][64];

    const float* A = blockIdx.z ? A1 : A0;
    float* Cp = C + (size_t)blockIdx.z * strideC;

    int tid = threadIdx.x;
    int tx = tid & 15, ty = tid >> 4;
    int row0 = blockIdx.y * 64, col0 = blockIdx.x * 64;

    float acc[4][4];
#pragma unroll
    for (int m = 0; m < 4; m++)
#pragma unroll
        for (int n = 0; n < 4; n++) acc[m][n] = 0.f;

    for (int k0 = 0; k0 < K; k0 += 32) {
#pragma unroll
        for (int i = tid; i < 64 * 32; i += 256) {
            int r = i >> 5, c = i & 31;
            As[c][r] = A[(size_t)(row0 + r) * K + k0 + c];
        }
#pragma unroll
        for (int i = tid; i < 32 * 64; i += 256) {
            int r = i >> 6, c = i & 63;
            Bs[r][c] = B[(size_t)(k0 + r) * N + col0 + c];
        }
        __syncthreads();
#pragma unroll
        for (int k = 0; k < 32; k++) {
            float a0 = As[k][ty * 4 + 0];
            float a1 = As[k][ty * 4 + 1];
            float a2 = As[k][ty * 4 + 2];
            float a3 = As[k][ty * 4 + 3];
            float4 b = *reinterpret_cast<const float4*>(&Bs[k][tx * 4]);
            acc[0][0] += a0 * b.x; acc[0][1] += a0 * b.y; acc[0][2] += a0 * b.z; acc[0][3] += a0 * b.w;
            acc[1][0] += a1 * b.x; acc[1][1] += a1 * b.y; acc[1][2] += a1 * b.z; acc[1][3] += a1 * b.w;
            acc[2][0] += a2 * b.x; acc[2][1] += a2 * b.y; acc[2][2] += a2 * b.z; acc[2][3] += a2 * b.w;
            acc[3][0] += a3 * b.x; acc[3][1] += a3 * b.y; acc[3][2] += a3 * b.z; acc[3][3] += a3 * b.w;
        }
        __syncthreads();
    }

    float bv0 = 0.f, bv1 = 0.f, bv2 = 0.f, bv3 = 0.f;
    if (bias) {
        bv0 = bias[col0 + tx * 4 + 0];
        bv1 = bias[col0 + tx * 4 + 1];
        bv2 = bias[col0 + tx * 4 + 2];
        bv3 = bias[col0 + tx * 4 + 3];
    }
#pragma unroll
    for (int m = 0; m < 4; m++) {
        float4 v;
        v.x = acc[m][0] + bv0; v.y = acc[m][1] + bv1;
        v.z = acc[m][2] + bv2; v.w = acc[m][3] + bv3;
        *reinterpret_cast<float4*>(&Cp[(size_t)(row0 + ty * 4 + m) * N + col0 + tx * 4]) = v;
    }
}

// ---------------- kNN: radius-filtered top-32 ----------------
// Key fact: reference masks neighbors beyond R to zero influence, so the effective
// set is the min(32, m) closest points within R. Filter pass is uniform (predicated
// smem compaction, ~59 hits/query expected), selection runs over the short buffer.
// d2 uses __f*_rn intrinsics to match the reference fp32 arithmetic exactly.
__global__ __launch_bounds__(KNN_TPB) void knn_kernel(
    const float* __restrict__ c0, const float* __restrict__ c1,
    int* __restrict__ out_idx, int* __restrict__ out_cnt)
{
    extern __shared__ char smraw[];
    float* bufd = (float*)smraw;                               // 64*161 floats
    int*   bufi = (int*)(smraw + 64 * 161 * 4);                // 64*161 ints
    float* bdv  = (float*)(smraw + 64 * 161 * 8);              // 64*33 floats
    int*   biv  = (int*)(smraw + 64 * 161 * 8 + 64 * 33 * 4);  // 64*33 ints
    float* sx   = (float*)(smraw + 64 * 161 * 8 + 64 * 33 * 8);
    float* sy = sx + 512;
    float* sz = sy + 512;

    int cl = blockIdx.y;
    const float* coords = cl ? c1 : c0;
    int tid = threadIdx.x;
    int q = blockIdx.x * KNN_TPB + tid;

    float qx = coords[3 * q], qy = coords[3 * q + 1], qz = coords[3 * q + 2];
    const float R2 = 0.0144f;  // RADIUS^2

    float* mybd = bufd + tid * 161;
    int*   mybi = bufi + tid * 161;
    int cnt = 0;

    for (int base = 0; base < NP; base += 512) {
        __syncthreads();
        for (int i = tid; i < 512; i += KNN_TPB) {
            int p = base + i;
            sx[i] = coords[3 * p];
            sy[i] = coords[3 * p + 1];
            sz[i] = coords[3 * p + 2];
        }
        __syncthreads();
#pragma unroll 4
        for (int j = 0; j < 512; j++) {
            float dx = __fsub_rn(qx, sx[j]);
            float dy = __fsub_rn(qy, sy[j]);
            float dz = __fsub_rn(qz, sz[j]);
            float d2 = __fadd_rn(__fadd_rn(__fmul_rn(dx, dx), __fmul_rn(dy, dy)),
                                 __fmul_rn(dz, dz));
            if (d2 <= R2 && cnt < BUFCAP) {
                mybd[cnt] = d2;
                mybi[cnt] = base + j;
                cnt++;
            }
        }
    }

    // select min(32, cnt) smallest (strict-less keeps earliest index on ties, like top_k)
    float* md = bdv + tid * 33;
    int*   mi = biv + tid * 33;
    int keep = cnt < 32 ? cnt : 32;
    for (int s = 0; s < keep; s++) { md[s] = mybd[s]; mi[s] = mybi[s]; }
    if (cnt > 32) {
        float cm = md[0]; int ca = 0;
        for (int s = 1; s < 32; s++) { float v = md[s]; if (v > cm) { cm = v; ca = s; } }
        for (int j = 32; j < cnt; j++) {
            float d = mybd[j];
            if (d < cm) {
                md[ca] = d; mi[ca] = mybi[j];
                cm = md[0]; ca = 0;
                for (int s = 1; s < 32; s++) { float v = md[s]; if (v > cm) { cm = v; ca = s; } }
            }
        }
    }

    int* oi = out_idx + ((size_t)cl * NP + q) * 32;
    for (int s = 0; s < 32; s++) oi[s] = (s < keep) ? mi[s] : 0;
    out_cnt[cl * NP + q] = keep;
}

// ---------------- KPConv aggregate: agg[n, p*64+c] = sum_k infl[k,p]*h[idx_k, c] ----------------
__global__ __launch_bounds__(256) void agg_kernel(
    const float* __restrict__ c0, const float* __restrict__ c1,
    const int* __restrict__ idx, const int* __restrict__ cntArr,
    const float* __restrict__ h, const float* __restrict__ kpts,
    float* __restrict__ agg)
{
    __shared__ __align__(16) float s_h[32][SCC];
    __shared__ float s_infl[32][16];
    __shared__ float s_kp[KPN][3];
    __shared__ float s_rel[32][3];
    __shared__ int s_idx[32];

    int cl = blockIdx.y;
    const float* coords = cl ? c1 : c0;
    int n = blockIdx.x;
    int tid = threadIdx.x;
    size_t qoff = (size_t)cl * NP + n;
    int cnt = cntArr[qoff];

    if (tid < KPN * 3) s_kp[tid / 3][tid % 3] = kpts[tid];
    if (tid < 32) s_idx[tid] = idx[qoff * 32 + tid];
    __syncthreads();

    if (tid < 32) {
        int j = s_idx[tid];
        s_rel[tid][0] = __fsub_rn(coords[3 * j],     coords[3 * n]);
        s_rel[tid][1] = __fsub_rn(coords[3 * j + 1], coords[3 * n + 1]);
        s_rel[tid][2] = __fsub_rn(coords[3 * j + 2], coords[3 * n + 2]);
    }
    __syncthreads();

    for (int e = tid; e < 32 * KPN; e += 256) {
        int k = e / KPN, p = e % KPN;
        float dx = s_rel[k][0] - s_kp[p][0];
        float dy = s_rel[k][1] - s_kp[p][1];
        float dz = s_rel[k][2] - s_kp[p][2];
        float dist = sqrtf(dx * dx + dy * dy + dz * dz);
        float w = fmaxf(1.0f - dist / 0.096f, 0.0f);    // EXTENT = 0.096
        s_infl[k][p] = (k < cnt) ? w : 0.0f;            // all kept neighbors are within R
    }

    const float* hcl = h + (size_t)cl * NP * SCC;
    for (int e = tid; e < 32 * SCC; e += 256) {
        int k = e >> 6, c = e & 63;
        s_h[k][c] = hcl[(size_t)s_idx[k] * SCC + c];    // pad idx=0 is masked by infl=0
    }
    __syncthreads();

    if (tid < 240) {
        int p = tid >> 4, c4 = (tid & 15) << 2;
        float a0 = 0.f, a1 = 0.f, a2 = 0.f, a3 = 0.f;
#pragma unroll
        for (int k = 0; k < 32; k++) {
            float w = s_infl[k][p];
            float4 hv = *reinterpret_cast<const float4*>(&s_h[k][c4]);
            a0 += w * hv.x; a1 += w * hv.y; a2 += w * hv.z; a3 += w * hv.w;
        }
        float* o = agg + qoff * (KPN * SCC) + p * SCC + c4;
        o[0] = a0; o[1] = a1; o[2] = a2; o[3] = a3;
    }
}

// ---------------- batch norm (deterministic two-pass) + leaky relu ----------------
__global__ __launch_bounds__(256) void bn_partial(const float* __restrict__ y,
                                                  float* __restrict__ part)
{
    int cl = blockIdx.y, b = blockIdx.x, ch = threadIdx.x;
    const float* p = y + (size_t)cl * NP * OUTC + (size_t)b * 256 * OUTC + ch;
    float s = 0.f, s2 = 0.f;
    for (int r = 0; r < 256; r++) {
        float v = p[(size_t)r * OUTC];
        s += v; s2 += v * v;
    }
    float* pp = part + (size_t)cl * 2 * 32 * OUTC;
    pp[b * OUTC + ch] = s;
    pp[32 * OUTC + b * OUTC + ch] = s2;
}

__global__ __launch_bounds__(256) void bn_final(const float* __restrict__ part,
                                                float* __restrict__ mu,
                                                float* __restrict__ rstd)
{
    int cl = blockIdx.x, ch = threadIdx.x;
    const float* pp = part + (size_t)cl * 2 * 32 * OUTC;
    float s = 0.f, s2 = 0.f;
    for (int b = 0; b < 32; b++) {
        s  += pp[b * OUTC + ch];
        s2 += pp[32 * OUTC + b * OUTC + ch];
    }
    float m = s * (1.0f / 8192.0f);
    float v = s2 * (1.0f / 8192.0f) - m * m;
    v = v < 0.f ? 0.f : v;
    mu[cl * OUTC + ch]   = m;
    rstd[cl * OUTC + ch] = rsqrtf(v + 1e-5f);
}

__global__ __launch_bounds__(256) void bn_apply(float* __restrict__ y,
                                                const float* __restrict__ mu,
                                                const float* __restrict__ rstd,
                                                const float* __restrict__ gamma,
                                                const float* __restrict__ beta)
{
    size_t i = (size_t)blockIdx.x * blockDim.x + threadIdx.x;  // over 2*NP*OUTC
    int ch = (int)(i & (OUTC - 1));
    int cl = (int)(i >> 21);  // NP*OUTC = 2^21
    float v = y[i];
    float t = gamma[ch] * (v - mu[cl * OUTC + ch]) * rstd[cl * OUTC + ch] + beta[ch];
    y[i] = t > 0.f ? t : 0.1f * t;
}

// ---------------- launch ----------------
extern "C" void kernel_launch(void* const* d_in, const int* in_sizes, int n_in,
                              void* d_out, int out_size)
{
    const float* src    = (const float*)d_in[0];
    const float* tgt    = (const float*)d_in[1];
    const float* src_c  = (const float*)d_in[2];
    const float* tgt_c  = (const float*)d_in[3];
    const float* W_in   = (const float*)d_in[4];
    const float* b_in   = (const float*)d_in[5];
    const float* kpts   = (const float*)d_in[6];
    const float* W_kp   = (const float*)d_in[7];
    const float* W_out  = (const float*)d_in[8];
    const float* b_out  = (const float*)d_in[9];
    const float* gamma  = (const float*)d_in[10];
    const float* beta   = (const float*)d_in[11];
    float* out = (float*)d_out;

    void* p;
    cudaGetSymbolAddress(&p, g_h);    float* hP    = (float*)p;
    cudaGetSymbolAddress(&p, g_idx);  int*   idxP  = (int*)p;
    cudaGetSymbolAddress(&p, g_cnt);  int*   cntP  = (int*)p;
    cudaGetSymbolAddress(&p, g_agg);  float* aggP  = (float*)p;
    cudaGetSymbolAddress(&p, g_h2);   float* h2P   = (float*)p;
    cudaGetSymbolAddress(&p, g_part); float* partP = (float*)p;
    cudaGetSymbolAddress(&p, g_mu);   float* muP   = (float*)p;
    cudaGetSymbolAddress(&p, g_rstd); float* rstdP = (float*)p;

    const int KNN_SMEM = 64 * 161 * 8 + 64 * 33 * 8 + 512 * 3 * 4;  // 105472 B
    cudaFuncSetAttribute(knn_kernel, cudaFuncAttributeMaxDynamicSharedMemorySize, KNN_SMEM);

    // 1) h = x @ W_in + b_in   ([8192,256]x[256,64], batched over clouds)
    gemm_k<<<dim3(1, 128, 2), 256>>>(src, tgt, W_in, b_in, hP,
                                     NP, SCC, INC, (size_t)NP * SCC);

    // 2) radius-filtered top-32 neighbor search
    knn_kernel<<<dim3(128, 2), KNN_TPB, KNN_SMEM>>>(src_c, tgt_c, idxP, cntP);

    // 3) KPConv influence-weighted aggregation -> agg [N, 960]
    agg_kernel<<<dim3(NP, 2), 256>>>(src_c, tgt_c, idxP, cntP, hP, kpts, aggP);

    // 4) h2 = agg @ W_kp  ([8192,960]x[960,64])
    gemm_k<<<dim3(1, 128, 2), 256>>>(aggP, aggP + (size_t)NP * KPN * SCC, W_kp, nullptr,
                                     h2P, NP, SCC, KPN * SCC, (size_t)NP * SCC);

    // 5) y = h2 @ W_out + b_out -> directly into d_out
    gemm_k<<<dim3(4, 128, 2), 256>>>(h2P, h2P + (size_t)NP * SCC, W_out, b_out,
                                     out, NP, OUTC, SCC, (size_t)NP * OUTC);

    // 6) batch norm (train-mode stats) + leaky relu, in place on d_out
    bn_partial<<<dim3(32, 2), 256>>>(out, partP);
    bn_final<<<2, 256>>>(partP, muP, rstdP);
    bn_apply<<<(2 * NP * OUTC) / 256, 256>>>(out, muP, rstdP, gamma, beta);

    // 7) coords pass-through
    cudaMemcpyAsync(out + (size_t)2 * NP * OUTC, src_c, NP * 3 * sizeof(float),
                    cudaMemcpyDeviceToDevice);
    cudaMemcpyAsync(out + (size_t)2 * NP * OUTC + NP * 3, tgt_c, NP * 3 * sizeof(float),
                    cudaMemcpyDeviceToDevice);
}

// round 3
// speedup vs baseline: 1.3311x; 1.3311x over previous
#include <cuda_runtime.h>
#include <math.h>

#define NP    8192
#define INC   256
#define SCC   64
#define OUTC  256
#define KPN   15

// ---------------- scratch (__device__ globals, no allocations) ----------------
__device__ __align__(256) float  g_h   [2 * NP * SCC];               // 4 MB
__device__ __align__(256) int    g_idx [2 * NP * 32];                // 2 MB
__device__ __align__(256) int    g_cnt [2 * NP];
__device__ __align__(256) float  g_agg [(size_t)2 * NP * KPN * SCC]; // 60 MB
__device__ __align__(256) float  g_h2  [2 * NP * SCC];               // 4 MB
__device__ __align__(256) float  g_part[2 * 2 * 32 * OUTC];
__device__ __align__(256) float  g_mu  [2 * OUTC];
__device__ __align__(256) float  g_rstd[2 * OUTC];
// spatial grid (8x8x8 = 512 cells per cloud)
__device__ __align__(256) int    g_cellcnt [2 * 512];   // counts, then reused pattern below
__device__ __align__(256) int    g_fill    [2 * 512];
__device__ __align__(256) int    g_cellstart[2 * 513];
__device__ __align__(256) float4 g_sorted  [2 * NP];    // xyz + original index (bits)

// ---------------- 128x64 tiled fp32 GEMM: C = A @ B (+bias) ----------------
// 256 threads, per-thread 8x4 accumulators. grid.z selects cloud.
__global__ __launch_bounds__(256) void gemm_k(
    const float* __restrict__ A0, const float* __restrict__ A1,
    const float* __restrict__ B,  const float* __restrict__ bias,
    float* __restrict__ C, int M, int N, int K, size_t strideC)
{
    __shared__ __align__(16) float As[32][132];  // [k][m], padded, 16B-aligned rows
    __shared__ __align__(16) float Bs[32][64];

    const float* A = blockIdx.z ? A1 : A0;
    float* Cp = C + (size_t)blockIdx.z * strideC;

    int tid = threadIdx.x;
    int tx = tid & 15;        // col group (x4)
    int ty = tid >> 4;        // row group (x8)
    int row0 = blockIdx.y * 128, col0 = blockIdx.x * 64;

    float acc[8][4];
#pragma unroll
    for (int m = 0; m < 8; m++)
#pragma unroll
        for (int n = 0; n < 4; n++) acc[m][n] = 0.f;

    for (int k0 = 0; k0 < K; k0 += 32) {
        // load A tile 128x32 (transposed into As[k][m]); 4 float4 per thread
#pragma unroll
        for (int pass = 0; pass < 4; pass++) {
            int idx = tid + pass * 256;          // float4 index 0..1023
            int r = idx >> 3, c4 = (idx & 7) * 4;
            float4 v = *reinterpret_cast<const float4*>(&A[(size_t)(row0 + r) * K + k0 + c4]);
            As[c4 + 0][r] = v.x; As[c4 + 1][r] = v.y;
            As[c4 + 2][r] = v.z; As[c4 + 3][r] = v.w;
        }
        // load B tile 32x64; 2 float4 per thread
#pragma unroll
        for (int pass = 0; pass < 2; pass++) {
            int idx = tid + pass * 256;          // float4 index 0..511
            int r = idx >> 4, c = (idx & 15) * 4;
            *reinterpret_cast<float4*>(&Bs[r][c]) =
                *reinterpret_cast<const float4*>(&B[(size_t)(k0 + r) * N + col0 + c]);
        }
        __syncthreads();
#pragma unroll
        for (int k = 0; k < 32; k++) {
            float4 a0 = *reinterpret_cast<const float4*>(&As[k][ty * 8]);
            float4 a1 = *reinterpret_cast<const float4*>(&As[k][ty * 8 + 4]);
            float4 b  = *reinterpret_cast<const float4*>(&Bs[k][tx * 4]);
            acc[0][0] += a0.x * b.x; acc[0][1] += a0.x * b.y; acc[0][2] += a0.x * b.z; acc[0][3] += a0.x * b.w;
            acc[1][0] += a0.y * b.x; acc[1][1] += a0.y * b.y; acc[1][2] += a0.y * b.z; acc[1][3] += a0.y * b.w;
            acc[2][0] += a0.z * b.x; acc[2][1] += a0.z * b.y; acc[2][2] += a0.z * b.z; acc[2][3] += a0.z * b.w;
            acc[3][0] += a0.w * b.x; acc[3][1] += a0.w * b.y; acc[3][2] += a0.w * b.z; acc[3][3] += a0.w * b.w;
            acc[4][0] += a1.x * b.x; acc[4][1] += a1.x * b.y; acc[4][2] += a1.x * b.z; acc[4][3] += a1.x * b.w;
            acc[5][0] += a1.y * b.x; acc[5][1] += a1.y * b.y; acc[5][2] += a1.y * b.z; acc[5][3] += a1.y * b.w;
            acc[6][0] += a1.z * b.x; acc[6][1] += a1.z * b.y; acc[6][2] += a1.z * b.z; acc[6][3] += a1.z * b.w;
            acc[7][0] += a1.w * b.x; acc[7][1] += a1.w * b.y; acc[7][2] += a1.w * b.z; acc[7][3] += a1.w * b.w;
        }
        __syncthreads();
    }

    float bv0 = 0.f, bv1 = 0.f, bv2 = 0.f, bv3 = 0.f;
    if (bias) {
        bv0 = bias[col0 + tx * 4 + 0];
        bv1 = bias[col0 + tx * 4 + 1];
        bv2 = bias[col0 + tx * 4 + 2];
        bv3 = bias[col0 + tx * 4 + 3];
    }
#pragma unroll
    for (int m = 0; m < 8; m++) {
        float4 v;
        v.x = acc[m][0] + bv0; v.y = acc[m][1] + bv1;
        v.z = acc[m][2] + bv2; v.w = acc[m][3] + bv3;
        *reinterpret_cast<float4*>(&Cp[(size_t)(row0 + ty * 8 + m) * N + col0 + tx * 4]) = v;
    }
}

// ---------------- spatial grid build ----------------
__device__ __forceinline__ int cell_of(float x, float y, float z) {
    int cx = (int)(x * 8.0f); cx = cx < 0 ? 0 : (cx > 7 ? 7 : cx);
    int cy = (int)(y * 8.0f); cy = cy < 0 ? 0 : (cy > 7 ? 7 : cy);
    int cz = (int)(z * 8.0f); cz = cz < 0 ? 0 : (cz > 7 ? 7 : cz);
    return (cz * 8 + cy) * 8 + cx;
}

__global__ __launch_bounds__(256) void grid_hist(
    const float* __restrict__ c0, const float* __restrict__ c1, int* __restrict__ cnt)
{
    int i = blockIdx.x * 256 + threadIdx.x;     // 0..16383
    int cl = i >> 13, p = i & (NP - 1);
    const float* c = cl ? c1 : c0;
    int cell = cell_of(c[3 * p], c[3 * p + 1], c[3 * p + 2]);
    atomicAdd(&cnt[cl * 512 + cell], 1);
}

__global__ __launch_bounds__(512) void grid_scan(
    const int* __restrict__ cnt, int* __restrict__ start)
{
    __shared__ int s[512];
    int cl = blockIdx.x, t = threadIdx.x;
    s[t] = cnt[cl * 512 + t];
    __syncthreads();
#pragma unroll
    for (int off = 1; off < 512; off <<= 1) {
        int v = (t >= off) ? s[t - off] : 0;
        __syncthreads();
        s[t] += v;
        __syncthreads();
    }
    start[cl * 513 + t + 1] = s[t];
    if (t == 0) start[cl * 513] = 0;
}

__global__ __launch_bounds__(256) void grid_scatter(
    const float* __restrict__ c0, const float* __restrict__ c1,
    const int* __restrict__ start, int* __restrict__ fill, float4* __restrict__ sorted)
{
    int i = blockIdx.x * 256 + threadIdx.x;
    int cl = i >> 13, p = i & (NP - 1);
    const float* c = cl ? c1 : c0;
    float x = c[3 * p], y = c[3 * p + 1], z = c[3 * p + 2];
    int cell = cell_of(x, y, z);
    int pos = start[cl * 513 + cell] + atomicAdd(&fill[cl * 512 + cell], 1);
    sorted[cl * NP + pos] = make_float4(x, y, z, __int_as_float(p));
}

// ---------------- kNN via grid: streaming radius-filtered top-32 ----------------
// The reference zeroes influence beyond R, so the effective neighbor set is
// exactly the min(32, m) nearest points within R. Cell=0.125 >= R so the
// 27-cell neighborhood covers the ball. Selection by distance is scan-order
// independent (no exact fp32 ties among random points), so atomic scatter
// order cannot change the output.
__global__ __launch_bounds__(256) void knn_grid(
    const float* __restrict__ c0, const float* __restrict__ c1,
    const int* __restrict__ start, const float4* __restrict__ sorted,
    int* __restrict__ out_idx, int* __restrict__ out_cnt)
{
    extern __shared__ char smraw[];
    float* smd = (float*)smraw;                    // 256*33 floats
    int*   smi = (int*)(smraw + 256 * 33 * 4);     // 256*33 ints

    int cl = blockIdx.y;
    const float* coords = cl ? c1 : c0;
    int tid = threadIdx.x;
    int q = blockIdx.x * 256 + tid;

    float qx = coords[3 * q], qy = coords[3 * q + 1], qz = coords[3 * q + 2];
    const float R2 = 0.0144f;

    int cx = (int)(qx * 8.0f); cx = cx < 0 ? 0 : (cx > 7 ? 7 : cx);
    int cy = (int)(qy * 8.0f); cy = cy < 0 ? 0 : (cy > 7 ? 7 : cy);
    int cz = (int)(qz * 8.0f); cz = cz < 0 ? 0 : (cz > 7 ? 7 : cz);
    int xlo = cx > 0 ? cx - 1 : 0, xhi = cx < 7 ? cx + 1 : 7;
    int ylo = cy > 0 ? cy - 1 : 0, yhi = cy < 7 ? cy + 1 : 7;
    int zlo = cz > 0 ? cz - 1 : 0, zhi = cz < 7 ? cz + 1 : 7;

    float* md = smd + tid * 33;
    int*   mi = smi + tid * 33;
    int keep = 0;
    float cm = 0.f; int ca = 0;
    const int* st = start + cl * 513;
    const float4* srt = sorted + (size_t)cl * NP;

    for (int z = zlo; z <= zhi; z++)
        for (int y = ylo; y <= yhi; y++) {
            int rowcell = (z * 8 + y) * 8;
            int jb = st[rowcell + xlo];
            int je = st[rowcell + xhi + 1];          // x-cells are contiguous
            for (int j = jb; j < je; j++) {
                float4 pc = srt[j];
                float dx = __fsub_rn(qx, pc.x);
                float dy = __fsub_rn(qy, pc.y);
                float dz = __fsub_rn(qz, pc.z);
                float d2 = __fadd_rn(__fadd_rn(__fmul_rn(dx, dx), __fmul_rn(dy, dy)),
                                     __fmul_rn(dz, dz));
                if (d2 <= R2) {
                    if (keep < 32) {
                        md[keep] = d2; mi[keep] = __float_as_int(pc.w); keep++;
                        if (keep == 32) {
                            cm = md[0]; ca = 0;
#pragma unroll
                            for (int s = 1; s < 32; s++) { float v = md[s]; if (v > cm) { cm = v; ca = s; } }
                        }
                    } else if (d2 < cm) {
                        md[ca] = d2; mi[ca] = __float_as_int(pc.w);
                        cm = md[0]; ca = 0;
#pragma unroll
                        for (int s = 1; s < 32; s++) { float v = md[s]; if (v > cm) { cm = v; ca = s; } }
                    }
                }
            }
        }

    int* oi = out_idx + ((size_t)cl * NP + q) * 32;
    for (int s = 0; s < 32; s++) oi[s] = (s < keep) ? mi[s] : 0;
    out_cnt[cl * NP + q] = keep;
}

// ---------------- KPConv aggregate: agg[n, p*64+c] = sum_k infl[k,p]*h[idx_k, c] ----------------
__global__ __launch_bounds__(256) void agg_kernel(
    const float* __restrict__ c0, const float* __restrict__ c1,
    const int* __restrict__ idx, const int* __restrict__ cntArr,
    const float* __restrict__ h, const float* __restrict__ kpts,
    float* __restrict__ agg)
{
    __shared__ __align__(16) float s_h[32][SCC];
    __shared__ float s_infl[32][16];
    __shared__ float s_kp[KPN][3];
    __shared__ float s_rel[32][3];
    __shared__ int s_idx[32];

    int cl = blockIdx.y;
    const float* coords = cl ? c1 : c0;
    int n = blockIdx.x;
    int tid = threadIdx.x;
    size_t qoff = (size_t)cl * NP + n;
    int cnt = cntArr[qoff];

    if (tid < KPN * 3) s_kp[tid / 3][tid % 3] = kpts[tid];
    if (tid < 32) s_idx[tid] = idx[qoff * 32 + tid];
    __syncthreads();

    if (tid < 32) {
        int j = s_idx[tid];
        s_rel[tid][0] = __fsub_rn(coords[3 * j],     coords[3 * n]);
        s_rel[tid][1] = __fsub_rn(coords[3 * j + 1], coords[3 * n + 1]);
        s_rel[tid][2] = __fsub_rn(coords[3 * j + 2], coords[3 * n + 2]);
    }
    __syncthreads();

    for (int e = tid; e < 32 * KPN; e += 256) {
        int k = e / KPN, p = e % KPN;
        float dx = s_rel[k][0] - s_kp[p][0];
        float dy = s_rel[k][1] - s_kp[p][1];
        float dz = s_rel[k][2] - s_kp[p][2];
        float dist = sqrtf(dx * dx + dy * dy + dz * dz);
        float w = fmaxf(1.0f - dist / 0.096f, 0.0f);    // EXTENT = 0.096
        s_infl[k][p] = (k < cnt) ? w : 0.0f;
    }

    const float* hcl = h + (size_t)cl * NP * SCC;
    for (int e = tid; e < 32 * SCC; e += 256) {
        int k = e >> 6, c = e & 63;
        s_h[k][c] = hcl[(size_t)s_idx[k] * SCC + c];
    }
    __syncthreads();

    if (tid < 240) {
        int p = tid >> 4, c4 = (tid & 15) << 2;
        float a0 = 0.f, a1 = 0.f, a2 = 0.f, a3 = 0.f;
#pragma unroll
        for (int k = 0; k < 32; k++) {
            float w = s_infl[k][p];
            float4 hv = *reinterpret_cast<const float4*>(&s_h[k][c4]);
            a0 += w * hv.x; a1 += w * hv.y; a2 += w * hv.z; a3 += w * hv.w;
        }
        float* o = agg + qoff * (KPN * SCC) + p * SCC + c4;
        o[0] = a0; o[1] = a1; o[2] = a2; o[3] = a3;
    }
}

// ---------------- batch norm (deterministic two-pass) + leaky relu ----------------
__global__ __launch_bounds__(256) void bn_partial(const float* __restrict__ y,
                                                  float* __restrict__ part)
{
    int cl = blockIdx.y, b = blockIdx.x, ch = threadIdx.x;
    const float* p = y + (size_t)cl * NP * OUTC + (size_t)b * 256 * OUTC + ch;
    float s = 0.f, s2 = 0.f;
    for (int r = 0; r < 256; r++) {
        float v = p[(size_t)r * OUTC];
        s += v; s2 += v * v;
    }
    float* pp = part + (size_t)cl * 2 * 32 * OUTC;
    pp[b * OUTC + ch] = s;
    pp[32 * OUTC + b * OUTC + ch] = s2;
}

__global__ __launch_bounds__(256) void bn_final(const float* __restrict__ part,
                                                float* __restrict__ mu,
                                                float* __restrict__ rstd)
{
    int cl = blockIdx.x, ch = threadIdx.x;
    const float* pp = part + (size_t)cl * 2 * 32 * OUTC;
    float s = 0.f, s2 = 0.f;
    for (int b = 0; b < 32; b++) {
        s  += pp[b * OUTC + ch];
        s2 += pp[32 * OUTC + b * OUTC + ch];
    }
    float m = s * (1.0f / 8192.0f);
    float v = s2 * (1.0f / 8192.0f) - m * m;
    v = v < 0.f ? 0.f : v;
    mu[cl * OUTC + ch]   = m;
    rstd[cl * OUTC + ch] = rsqrtf(v + 1e-5f);
}

__global__ __launch_bounds__(256) void bn_apply(float* __restrict__ y,
                                                const float* __restrict__ mu,
                                                const float* __restrict__ rstd,
                                                const float* __restrict__ gamma,
                                                const float* __restrict__ beta)
{
    size_t i = (size_t)blockIdx.x * blockDim.x + threadIdx.x;
    int ch = (int)(i & (OUTC - 1));
    int cl = (int)(i >> 21);
    float v = y[i];
    float t = gamma[ch] * (v - mu[cl * OUTC + ch]) * rstd[cl * OUTC + ch] + beta[ch];
    y[i] = t > 0.f ? t : 0.1f * t;
}

// ---------------- launch ----------------
extern "C" void kernel_launch(void* const* d_in, const int* in_sizes, int n_in,
                              void* d_out, int out_size)
{
    const float* src    = (const float*)d_in[0];
    const float* tgt    = (const float*)d_in[1];
    const float* src_c  = (const float*)d_in[2];
    const float* tgt_c  = (const float*)d_in[3];
    const float* W_in   = (const float*)d_in[4];
    const float* b_in   = (const float*)d_in[5];
    const float* kpts   = (const float*)d_in[6];
    const float* W_kp   = (const float*)d_in[7];
    const float* W_out  = (const float*)d_in[8];
    const float* b_out  = (const float*)d_in[9];
    const float* gamma  = (const float*)d_in[10];
    const float* beta   = (const float*)d_in[11];
    float* out = (float*)d_out;

    void* p;
    cudaGetSymbolAddress(&p, g_h);        float*  hP    = (float*)p;
    cudaGetSymbolAddress(&p, g_idx);      int*    idxP  = (int*)p;
    cudaGetSymbolAddress(&p, g_cnt);      int*    cntP  = (int*)p;
    cudaGetSymbolAddress(&p, g_agg);      float*  aggP  = (float*)p;
    cudaGetSymbolAddress(&p, g_h2);       float*  h2P   = (float*)p;
    cudaGetSymbolAddress(&p, g_part);     float*  partP = (float*)p;
    cudaGetSymbolAddress(&p, g_mu);       float*  muP   = (float*)p;
    cudaGetSymbolAddress(&p, g_rstd);     float*  rstdP = (float*)p;
    cudaGetSymbolAddress(&p, g_cellcnt);  int*    ccntP = (int*)p;
    cudaGetSymbolAddress(&p, g_fill);     int*    fillP = (int*)p;
    cudaGetSymbolAddress(&p, g_cellstart);int*    cstP  = (int*)p;
    cudaGetSymbolAddress(&p, g_sorted);   float4* srtP  = (float4*)p;

    const int KNN_SMEM = 256 * 33 * 8;   // 67584 B
    cudaFuncSetAttribute(knn_grid, cudaFuncAttributeMaxDynamicSharedMemorySize, KNN_SMEM);

    // --- spatial grid build (both clouds) ---
    cudaMemsetAsync(ccntP, 0, 2 * 512 * sizeof(int));
    cudaMemsetAsync(fillP, 0, 2 * 512 * sizeof(int));
    grid_hist<<<64, 256>>>(src_c, tgt_c, ccntP);
    grid_scan<<<2, 512>>>(ccntP, cstP);
    grid_scatter<<<64, 256>>>(src_c, tgt_c, cstP, fillP, srtP);

    // 1) h = x @ W_in + b_in   ([8192,256]x[256,64], both clouds)
    gemm_k<<<dim3(1, 64, 2), 256>>>(src, tgt, W_in, b_in, hP,
                                    NP, SCC, INC, (size_t)NP * SCC);

    // 2) grid-accelerated radius-filtered top-32
    knn_grid<<<dim3(32, 2), 256, KNN_SMEM>>>(src_c, tgt_c, cstP, srtP, idxP, cntP);

    // 3) KPConv influence-weighted aggregation -> agg [N, 960]
    agg_kernel<<<dim3(NP, 2), 256>>>(src_c, tgt_c, idxP, cntP, hP, kpts, aggP);

    // 4) h2 = agg @ W_kp  ([8192,960]x[960,64])
    gemm_k<<<dim3(1, 64, 2), 256>>>(aggP, aggP + (size_t)NP * KPN * SCC, W_kp, nullptr,
                                    h2P, NP, SCC, KPN * SCC, (size_t)NP * SCC);

    // 5) y = h2 @ W_out + b_out -> directly into d_out
    gemm_k<<<dim3(4, 64, 2), 256>>>(h2P, h2P + (size_t)NP * SCC, W_out, b_out,
                                    out, NP, OUTC, SCC, (size_t)NP * OUTC);

    // 6) batch norm (train-mode stats) + leaky relu, in place on d_out
    bn_partial<<<dim3(32, 2), 256>>>(out, partP);
    bn_final<<<2, 256>>>(partP, muP, rstdP);
    bn_apply<<<(2 * NP * OUTC) / 256, 256>>>(out, muP, rstdP, gamma, beta);

    // 7) coords pass-through
    cudaMemcpyAsync(out + (size_t)2 * NP * OUTC, src_c, NP * 3 * sizeof(float),
                    cudaMemcpyDeviceToDevice);
    cudaMemcpyAsync(out + (size_t)2 * NP * OUTC + NP * 3, tgt_c, NP * 3 * sizeof(float),
                    cudaMemcpyDeviceToDevice);
}

// round 4
// speedup vs baseline: 1.6404x; 1.2324x over previous
#include <cuda_runtime.h>
#include <math.h>

#define NP    8192
#define INC   256
#define SCC   64
#define OUTC  256
#define KPN   15
#define AGG_PTS 16

// ---------------- scratch (__device__ globals, no allocations) ----------------
__device__ __align__(256) float  g_h   [2 * NP * SCC];               // 4 MB
__device__ __align__(256) int    g_idx [2 * NP * 32];                // 2 MB
__device__ __align__(256) int    g_cnt [2 * NP];
__device__ __align__(256) float  g_agg [(size_t)2 * NP * KPN * SCC]; // 60 MB
__device__ __align__(256) float  g_h2  [2 * NP * SCC];               // 4 MB
__device__ __align__(256) float  g_part[2 * 2 * 32 * OUTC];
__device__ __align__(256) float  g_mu  [2 * OUTC];
__device__ __align__(256) float  g_rstd[2 * OUTC];
// spatial grid (8x8x8 = 512 cells per cloud)
__device__ __align__(256) int    g_cellcnt  [2 * 512];
__device__ __align__(256) int    g_fill     [2 * 512];
__device__ __align__(256) int    g_cellstart[2 * 513];
__device__ __align__(256) float4 g_sorted   [2 * NP];   // xyz + original index (bits)

// ---------------- 128x64 tiled fp32 GEMM, double-buffered ----------------
// 256 threads, per-thread 8x4 accumulators. grid.z selects cloud.
#define GEMM_SMEM (2 * (32 * 132 + 32 * 64) * 4)   // 50176 B dynamic

__global__ __launch_bounds__(256) void gemm_k(
    const float* __restrict__ A0, const float* __restrict__ A1,
    const float* __restrict__ B,  const float* __restrict__ bias,
    float* __restrict__ C, int M, int N, int K, size_t strideC)
{
    extern __shared__ float smem_g[];
    float (*As)[32][132] = (float (*)[32][132])smem_g;                  // [buf][k][m]
    float (*Bs)[32][64]  = (float (*)[32][64])(smem_g + 2 * 32 * 132);  // [buf][k][n]

    const float* A = blockIdx.z ? A1 : A0;
    float* Cp = C + (size_t)blockIdx.z * strideC;

    int tid = threadIdx.x;
    int tx = tid & 15;        // col group (x4)
    int ty = tid >> 4;        // row group (x8)
    int row0 = blockIdx.y * 128, col0 = blockIdx.x * 64;

    float acc[8][4];
#pragma unroll
    for (int m = 0; m < 8; m++)
#pragma unroll
        for (int n = 0; n < 4; n++) acc[m][n] = 0.f;

    // per-thread staging registers
    float4 a_reg[4], b_reg[2];
    int ar[4], ac[4], br[2], bc[2];
#pragma unroll
    for (int pass = 0; pass < 4; pass++) {
        int idx = tid + pass * 256;
        ar[pass] = idx >> 3; ac[pass] = (idx & 7) * 4;
    }
#pragma unroll
    for (int pass = 0; pass < 2; pass++) {
        int idx = tid + pass * 256;
        br[pass] = idx >> 4; bc[pass] = (idx & 15) * 4;
    }

    const int KT = K >> 5;

    // prologue: load tile 0
#pragma unroll
    for (int pass = 0; pass < 4; pass++)
        a_reg[pass] = *reinterpret_cast<const float4*>(&A[(size_t)(row0 + ar[pass]) * K + ac[pass]]);
#pragma unroll
    for (int pass = 0; pass < 2; pass++)
        b_reg[pass] = *reinterpret_cast<const float4*>(&B[(size_t)br[pass] * N + col0 + bc[pass]]);
#pragma unroll
    for (int pass = 0; pass < 4; pass++) {
        As[0][ac[pass] + 0][ar[pass]] = a_reg[pass].x;
        As[0][ac[pass] + 1][ar[pass]] = a_reg[pass].y;
        As[0][ac[pass] + 2][ar[pass]] = a_reg[pass].z;
        As[0][ac[pass] + 3][ar[pass]] = a_reg[pass].w;
    }
#pragma unroll
    for (int pass = 0; pass < 2; pass++)
        *reinterpret_cast<float4*>(&Bs[0][br[pass]][bc[pass]]) = b_reg[pass];
    __syncthreads();

    for (int kt = 0; kt < KT; kt++) {
        int cur = kt & 1;
        int k0n = (kt + 1) << 5;
        if (kt + 1 < KT) {
#pragma unroll
            for (int pass = 0; pass < 4; pass++)
                a_reg[pass] = *reinterpret_cast<const float4*>(
                    &A[(size_t)(row0 + ar[pass]) * K + k0n + ac[pass]]);
#pragma unroll
            for (int pass = 0; pass < 2; pass++)
                b_reg[pass] = *reinterpret_cast<const float4*>(
                    &B[(size_t)(k0n + br[pass]) * N + col0 + bc[pass]]);
        }
#pragma unroll
        for (int k = 0; k < 32; k++) {
            float4 a0 = *reinterpret_cast<const float4*>(&As[cur][k][ty * 8]);
            float4 a1 = *reinterpret_cast<const float4*>(&As[cur][k][ty * 8 + 4]);
            float4 b  = *reinterpret_cast<const float4*>(&Bs[cur][k][tx * 4]);
            acc[0][0] += a0.x * b.x; acc[0][1] += a0.x * b.y; acc[0][2] += a0.x * b.z; acc[0][3] += a0.x * b.w;
            acc[1][0] += a0.y * b.x; acc[1][1] += a0.y * b.y; acc[1][2] += a0.y * b.z; acc[1][3] += a0.y * b.w;
            acc[2][0] += a0.z * b.x; acc[2][1] += a0.z * b.y; acc[2][2] += a0.z * b.z; acc[2][3] += a0.z * b.w;
            acc[3][0] += a0.w * b.x; acc[3][1] += a0.w * b.y; acc[3][2] += a0.w * b.z; acc[3][3] += a0.w * b.w;
            acc[4][0] += a1.x * b.x; acc[4][1] += a1.x * b.y; acc[4][2] += a1.x * b.z; acc[4][3] += a1.x * b.w;
            acc[5][0] += a1.y * b.x; acc[5][1] += a1.y * b.y; acc[5][2] += a1.y * b.z; acc[5][3] += a1.y * b.w;
            acc[6][0] += a1.z * b.x; acc[6][1] += a1.z * b.y; acc[6][2] += a1.z * b.z; acc[6][3] += a1.z * b.w;
            acc[7][0] += a1.w * b.x; acc[7][1] += a1.w * b.y; acc[7][2] += a1.w * b.z; acc[7][3] += a1.w * b.w;
        }
        if (kt + 1 < KT) {
            int nxt = (kt + 1) & 1;
#pragma unroll
            for (int pass = 0; pass < 4; pass++) {
                As[nxt][ac[pass] + 0][ar[pass]] = a_reg[pass].x;
                As[nxt][ac[pass] + 1][ar[pass]] = a_reg[pass].y;
                As[nxt][ac[pass] + 2][ar[pass]] = a_reg[pass].z;
                As[nxt][ac[pass] + 3][ar[pass]] = a_reg[pass].w;
            }
#pragma unroll
            for (int pass = 0; pass < 2; pass++)
                *reinterpret_cast<float4*>(&Bs[nxt][br[pass]][bc[pass]]) = b_reg[pass];
            __syncthreads();
        }
    }

    float bv0 = 0.f, bv1 = 0.f, bv2 = 0.f, bv3 = 0.f;
    if (bias) {
        bv0 = bias[col0 + tx * 4 + 0];
        bv1 = bias[col0 + tx * 4 + 1];
        bv2 = bias[col0 + tx * 4 + 2];
        bv3 = bias[col0 + tx * 4 + 3];
    }
#pragma unroll
    for (int m = 0; m < 8; m++) {
        float4 v;
        v.x = acc[m][0] + bv0; v.y = acc[m][1] + bv1;
        v.z = acc[m][2] + bv2; v.w = acc[m][3] + bv3;
        *reinterpret_cast<float4*>(&Cp[(size_t)(row0 + ty * 8 + m) * N + col0 + tx * 4]) = v;
    }
}

// ---------------- spatial grid build ----------------
__device__ __forceinline__ int cell_of(float x, float y, float z) {
    int cx = (int)(x * 8.0f); cx = cx < 0 ? 0 : (cx > 7 ? 7 : cx);
    int cy = (int)(y * 8.0f); cy = cy < 0 ? 0 : (cy > 7 ? 7 : cy);
    int cz = (int)(z * 8.0f); cz = cz < 0 ? 0 : (cz > 7 ? 7 : cz);
    return (cz * 8 + cy) * 8 + cx;
}

__global__ __launch_bounds__(256) void grid_hist(
    const float* __restrict__ c0, const float* __restrict__ c1, int* __restrict__ cnt)
{
    int i = blockIdx.x * 256 + threadIdx.x;
    int cl = i >> 13, p = i & (NP - 1);
    const float* c = cl ? c1 : c0;
    int cell = cell_of(c[3 * p], c[3 * p + 1], c[3 * p + 2]);
    atomicAdd(&cnt[cl * 512 + cell], 1);
}

__global__ __launch_bounds__(512) void grid_scan(
    const int* __restrict__ cnt, int* __restrict__ start)
{
    __shared__ int s[512];
    int cl = blockIdx.x, t = threadIdx.x;
    s[t] = cnt[cl * 512 + t];
    __syncthreads();
#pragma unroll
    for (int off = 1; off < 512; off <<= 1) {
        int v = (t >= off) ? s[t - off] : 0;
        __syncthreads();
        s[t] += v;
        __syncthreads();
    }
    start[cl * 513 + t + 1] = s[t];
    if (t == 0) start[cl * 513] = 0;
}

__global__ __launch_bounds__(256) void grid_scatter(
    const float* __restrict__ c0, const float* __restrict__ c1,
    const int* __restrict__ start, int* __restrict__ fill, float4* __restrict__ sorted)
{
    int i = blockIdx.x * 256 + threadIdx.x;
    int cl = i >> 13, p = i & (NP - 1);
    const float* c = cl ? c1 : c0;
    float x = c[3 * p], y = c[3 * p + 1], z = c[3 * p + 2];
    int cell = cell_of(x, y, z);
    int pos = start[cl * 513 + cell] + atomicAdd(&fill[cl * 512 + cell], 1);
    sorted[cl * NP + pos] = make_float4(x, y, z, __int_as_float(p));
}

// ---------------- kNN via grid: streaming radius-filtered top-32 ----------------
__global__ __launch_bounds__(256) void knn_grid(
    const float* __restrict__ c0, const float* __restrict__ c1,
    const int* __restrict__ start, const float4* __restrict__ sorted,
    int* __restrict__ out_idx, int* __restrict__ out_cnt)
{
    extern __shared__ char smraw[];
    float* smd = (float*)smraw;                    // 256*33 floats
    int*   smi = (int*)(smraw + 256 * 33 * 4);     // 256*33 ints

    int cl = blockIdx.y;
    const float* coords = cl ? c1 : c0;
    int tid = threadIdx.x;
    int q = blockIdx.x * 256 + tid;

    float qx = coords[3 * q], qy = coords[3 * q + 1], qz = coords[3 * q + 2];
    const float R2 = 0.0144f;

    int cx = (int)(qx * 8.0f); cx = cx < 0 ? 0 : (cx > 7 ? 7 : cx);
    int cy = (int)(qy * 8.0f); cy = cy < 0 ? 0 : (cy > 7 ? 7 : cy);
    int cz = (int)(qz * 8.0f); cz = cz < 0 ? 0 : (cz > 7 ? 7 : cz);
    int xlo = cx > 0 ? cx - 1 : 0, xhi = cx < 7 ? cx + 1 : 7;
    int ylo = cy > 0 ? cy - 1 : 0, yhi = cy < 7 ? cy + 1 : 7;
    int zlo = cz > 0 ? cz - 1 : 0, zhi = cz < 7 ? cz + 1 : 7;

    float* md = smd + tid * 33;
    int*   mi = smi + tid * 33;
    int keep = 0;
    float cm = 0.f; int ca = 0;
    const int* st = start + cl * 513;
    const float4* srt = sorted + (size_t)cl * NP;

    for (int z = zlo; z <= zhi; z++)
        for (int y = ylo; y <= yhi; y++) {
            int rowcell = (z * 8 + y) * 8;
            int jb = st[rowcell + xlo];
            int je = st[rowcell + xhi + 1];
            for (int j = jb; j < je; j++) {
                float4 pc = srt[j];
                float dx = __fsub_rn(qx, pc.x);
                float dy = __fsub_rn(qy, pc.y);
                float dz = __fsub_rn(qz, pc.z);
                float d2 = __fadd_rn(__fadd_rn(__fmul_rn(dx, dx), __fmul_rn(dy, dy)),
                                     __fmul_rn(dz, dz));
                if (d2 <= R2) {
                    if (keep < 32) {
                        md[keep] = d2; mi[keep] = __float_as_int(pc.w); keep++;
                        if (keep == 32) {
                            cm = md[0]; ca = 0;
#pragma unroll
                            for (int s = 1; s < 32; s++) { float v = md[s]; if (v > cm) { cm = v; ca = s; } }
                        }
                    } else if (d2 < cm) {
                        md[ca] = d2; mi[ca] = __float_as_int(pc.w);
                        cm = md[0]; ca = 0;
#pragma unroll
                        for (int s = 1; s < 32; s++) { float v = md[s]; if (v > cm) { cm = v; ca = s; } }
                    }
                }
            }
        }

    int* oi = out_idx + ((size_t)cl * NP + q) * 32;
    for (int s = 0; s < 32; s++) oi[s] = (s < keep) ? mi[s] : 0;
    out_cnt[cl * NP + q] = keep;
}

// ---------------- KPConv aggregate (register-resident, 16 pts/block) ----------------
// thread = (local point pt = tid>>4, c4 = (tid&15)*4); all 15 kernel-point
// accumulators live in registers; neighbor features come straight from global
// (half-warp covers a contiguous 256B row -> coalesced); influences are
// broadcast LDS.32. FMA:LDS ratio 60:16 per k-step.
__global__ __launch_bounds__(256) void agg_kernel(
    const float* __restrict__ c0, const float* __restrict__ c1,
    const int* __restrict__ idx, const int* __restrict__ cntArr,
    const float* __restrict__ h, const float* __restrict__ kpts,
    float* __restrict__ agg)
{
    __shared__ float s_infl[AGG_PTS][32][KPN];   // 30720 B
    __shared__ int   s_idx[AGG_PTS][32];
    __shared__ float s_rel[AGG_PTS][32][3];
    __shared__ float s_kp[KPN][3];
    __shared__ int   s_cnt[AGG_PTS];

    int cl = blockIdx.y;
    const float* coords = cl ? c1 : c0;
    int p0 = blockIdx.x * AGG_PTS;
    int tid = threadIdx.x;
    size_t qbase = (size_t)cl * NP + p0;

    if (tid < KPN * 3) s_kp[tid / 3][tid % 3] = kpts[tid];
    if (tid < AGG_PTS) s_cnt[tid] = cntArr[qbase + tid];
#pragma unroll
    for (int s = 0; s < 2; s++) {
        int i = tid + s * 256;            // 512 (pt,k) pairs
        int pt = i >> 5, k = i & 31;
        s_idx[pt][k] = idx[(qbase + pt) * 32 + k];
    }
    __syncthreads();

#pragma unroll
    for (int s = 0; s < 2; s++) {
        int i = tid + s * 256;
        int pt = i >> 5, k = i & 31;
        int j = s_idx[pt][k], n = p0 + pt;
        s_rel[pt][k][0] = __fsub_rn(coords[3 * j],     coords[3 * n]);
        s_rel[pt][k][1] = __fsub_rn(coords[3 * j + 1], coords[3 * n + 1]);
        s_rel[pt][k][2] = __fsub_rn(coords[3 * j + 2], coords[3 * n + 2]);
    }
    __syncthreads();

#pragma unroll
    for (int s = 0; s < 2; s++) {
        int i = tid + s * 256;
        int pt = i >> 5, k = i & 31;
        float rx = s_rel[pt][k][0], ry = s_rel[pt][k][1], rz = s_rel[pt][k][2];
        bool valid = k < s_cnt[pt];
#pragma unroll
        for (int p = 0; p < KPN; p++) {
            float dx = rx - s_kp[p][0];
            float dy = ry - s_kp[p][1];
            float dz = rz - s_kp[p][2];
            float dist = sqrtf(dx * dx + dy * dy + dz * dz);
            float w = fmaxf(1.0f - dist * (1.0f / 0.096f), 0.0f);
            s_infl[pt][k][p] = valid ? w : 0.0f;
        }
    }
    __syncthreads();

    int pt = tid >> 4;
    int c4 = (tid & 15) << 2;
    const float* hcl = h + (size_t)cl * NP * SCC;

    float acc[KPN][4];
#pragma unroll
    for (int p = 0; p < KPN; p++)
#pragma unroll
        for (int d = 0; d < 4; d++) acc[p][d] = 0.f;

    float4 hv = *reinterpret_cast<const float4*>(&hcl[(size_t)s_idx[pt][0] * SCC + c4]);
#pragma unroll
    for (int k = 0; k < 32; k++) {
        float4 nxt;
        if (k < 31)
            nxt = *reinterpret_cast<const float4*>(&hcl[(size_t)s_idx[pt][k + 1] * SCC + c4]);
#pragma unroll
        for (int p = 0; p < KPN; p++) {
            float w = s_infl[pt][k][p];
            acc[p][0] += w * hv.x; acc[p][1] += w * hv.y;
            acc[p][2] += w * hv.z; acc[p][3] += w * hv.w;
        }
        hv = nxt;
    }

    float* o = agg + (qbase + pt) * (KPN * SCC) + c4;
#pragma unroll
    for (int p = 0; p < KPN; p++) {
        float4 v; v.x = acc[p][0]; v.y = acc[p][1]; v.z = acc[p][2]; v.w = acc[p][3];
        *reinterpret_cast<float4*>(&o[p * SCC]) = v;
    }
}

// ---------------- batch norm (deterministic two-pass) + leaky relu ----------------
__global__ __launch_bounds__(256) void bn_partial(const float* __restrict__ y,
                                                  float* __restrict__ part)
{
    int cl = blockIdx.y, b = blockIdx.x, ch = threadIdx.x;
    const float* p = y + (size_t)cl * NP * OUTC + (size_t)b * 256 * OUTC + ch;
    float s = 0.f, s2 = 0.f;
    for (int r = 0; r < 256; r++) {
        float v = p[(size_t)r * OUTC];
        s += v; s2 += v * v;
    }
    float* pp = part + (size_t)cl * 2 * 32 * OUTC;
    pp[b * OUTC + ch] = s;
    pp[32 * OUTC + b * OUTC + ch] = s2;
}

__global__ __launch_bounds__(256) void bn_final(const float* __restrict__ part,
                                                float* __restrict__ mu,
                                                float* __restrict__ rstd)
{
    int cl = blockIdx.x, ch = threadIdx.x;
    const float* pp = part + (size_t)cl * 2 * 32 * OUTC;
    float s = 0.f, s2 = 0.f;
    for (int b = 0; b < 32; b++) {
        s  += pp[b * OUTC + ch];
        s2 += pp[32 * OUTC + b * OUTC + ch];
    }
    float m = s * (1.0f / 8192.0f);
    float v = s2 * (1.0f / 8192.0f) - m * m;
    v = v < 0.f ? 0.f : v;
    mu[cl * OUTC + ch]   = m;
    rstd[cl * OUTC + ch] = rsqrtf(v + 1e-5f);
}

__global__ __launch_bounds__(256) void bn_apply(float* __restrict__ y,
                                                const float* __restrict__ mu,
                                                const float* __restrict__ rstd,
                                                const float* __restrict__ gamma,
                                                const float* __restrict__ beta)
{
    size_t i = (size_t)blockIdx.x * blockDim.x + threadIdx.x;
    int ch = (int)(i & (OUTC - 1));
    int cl = (int)(i >> 21);
    float v = y[i];
    float t = gamma[ch] * (v - mu[cl * OUTC + ch]) * rstd[cl * OUTC + ch] + beta[ch];
    y[i] = t > 0.f ? t : 0.1f * t;
}

// ---------------- launch ----------------
extern "C" void kernel_launch(void* const* d_in, const int* in_sizes, int n_in,
                              void* d_out, int out_size)
{
    const float* src    = (const float*)d_in[0];
    const float* tgt    = (const float*)d_in[1];
    const float* src_c  = (const float*)d_in[2];
    const float* tgt_c  = (const float*)d_in[3];
    const float* W_in   = (const float*)d_in[4];
    const float* b_in   = (const float*)d_in[5];
    const float* kpts   = (const float*)d_in[6];
    const float* W_kp   = (const float*)d_in[7];
    const float* W_out  = (const float*)d_in[8];
    const float* b_out  = (const float*)d_in[9];
    const float* gamma  = (const float*)d_in[10];
    const float* beta   = (const float*)d_in[11];
    float* out = (float*)d_out;

    void* p;
    cudaGetSymbolAddress(&p, g_h);        float*  hP    = (float*)p;
    cudaGetSymbolAddress(&p, g_idx);      int*    idxP  = (int*)p;
    cudaGetSymbolAddress(&p, g_cnt);      int*    cntP  = (int*)p;
    cudaGetSymbolAddress(&p, g_agg);      float*  aggP  = (float*)p;
    cudaGetSymbolAddress(&p, g_h2);       float*  h2P   = (float*)p;
    cudaGetSymbolAddress(&p, g_part);     float*  partP = (float*)p;
    cudaGetSymbolAddress(&p, g_mu);       float*  muP   = (float*)p;
    cudaGetSymbolAddress(&p, g_rstd);     float*  rstdP = (float*)p;
    cudaGetSymbolAddress(&p, g_cellcnt);  int*    ccntP = (int*)p;
    cudaGetSymbolAddress(&p, g_fill);     int*    fillP = (int*)p;
    cudaGetSymbolAddress(&p, g_cellstart);int*    cstP  = (int*)p;
    cudaGetSymbolAddress(&p, g_sorted);   float4* srtP  = (float4*)p;

    const int KNN_SMEM = 256 * 33 * 8;   // 67584 B
    cudaFuncSetAttribute(knn_grid, cudaFuncAttributeMaxDynamicSharedMemorySize, KNN_SMEM);
    cudaFuncSetAttribute(gemm_k, cudaFuncAttributeMaxDynamicSharedMemorySize, GEMM_SMEM);

    // --- spatial grid build (both clouds) ---
    cudaMemsetAsync(ccntP, 0, 2 * 512 * sizeof(int));
    cudaMemsetAsync(fillP, 0, 2 * 512 * sizeof(int));
    grid_hist<<<64, 256>>>(src_c, tgt_c, ccntP);
    grid_scan<<<2, 512>>>(ccntP, cstP);
    grid_scatter<<<64, 256>>>(src_c, tgt_c, cstP, fillP, srtP);

    // 1) h = x @ W_in + b_in
    gemm_k<<<dim3(1, 64, 2), 256, GEMM_SMEM>>>(src, tgt, W_in, b_in, hP,
                                               NP, SCC, INC, (size_t)NP * SCC);

    // 2) grid-accelerated radius-filtered top-32
    knn_grid<<<dim3(32, 2), 256, KNN_SMEM>>>(src_c, tgt_c, cstP, srtP, idxP, cntP);

    // 3) KPConv influence-weighted aggregation -> agg [N, 960]
    agg_kernel<<<dim3(NP / AGG_PTS, 2), 256>>>(src_c, tgt_c, idxP, cntP, hP, kpts, aggP);

    // 4) h2 = agg @ W_kp  ([8192,960]x[960,64])
    gemm_k<<<dim3(1, 64, 2), 256, GEMM_SMEM>>>(aggP, aggP + (size_t)NP * KPN * SCC, W_kp,
                                               nullptr, h2P, NP, SCC, KPN * SCC,
                                               (size_t)NP * SCC);

    // 5) y = h2 @ W_out + b_out -> directly into d_out
    gemm_k<<<dim3(4, 64, 2), 256, GEMM_SMEM>>>(h2P, h2P + (size_t)NP * SCC, W_out, b_out,
                                               out, NP, OUTC, SCC, (size_t)NP * OUTC);

    // 6) batch norm (train-mode stats) + leaky relu, in place on d_out
    bn_partial<<<dim3(32, 2), 256>>>(out, partP);
    bn_final<<<2, 256>>>(partP, muP, rstdP);
    bn_apply<<<(2 * NP * OUTC) / 256, 256>>>(out, muP, rstdP, gamma, beta);

    // 7) coords pass-through
    cudaMemcpyAsync(out + (size_t)2 * NP * OUTC, src_c, NP * 3 * sizeof(float),
                    cudaMemcpyDeviceToDevice);
    cudaMemcpyAsync(out + (size_t)2 * NP * OUTC + NP * 3, tgt_c, NP * 3 * sizeof(float),
                    cudaMemcpyDeviceToDevice);
}